// round 8
// baseline (speedup 1.0000x reference)
#include <cuda_runtime.h>
#include <cuda_bf16.h>
#include <cstdint>

// ---------------- problem constants ----------------
#define B_   16
#define C_   64
#define H_   192
#define W_   192
#define NPIX (H_ * W_)

// ---------------- tiling ----------------
#define TR 8                   // tile rows
#define TC 64                  // tile cols (512 px, 64 oc per tile)
#define HR 10                  // halo rows
#define HC 66                  // halo cols (used; padded to 68)
#define ROWB  544              // 68 cols * 8B (word pair e0,e1)
#define PSLOT 5456             // HR*ROWB + 16 pad (bank stagger)
#define LOB   (4 * PSLOT)      // lo image offset within a group (21824)
#define GRPB  (8 * PSLOT)      // one kf-group: 4 p-slots hi + 4 lo (43648)
#define NRING 5
#define RINGB (NRING * GRPB)   // 218240 B smem
#define THREADS 512
#define TPC 8                  // tiles per CTA

// Pre-packed W fragments: [b][tap][kf][hl][mf][lane] uint4 (mma A-frag order)
__device__ uint4 g_wfrag[B_ * 9 * 4 * 2 * 4 * 32];

// ---------------- helpers ----------------
__device__ __forceinline__ uint32_t smem_u32(const void* p) {
    uint32_t a;
    asm("{ .reg .u64 t; cvta.to.shared.u64 t, %1; cvt.u32.u64 %0, t; }" : "=r"(a) : "l"(p));
    return a;
}
__device__ __forceinline__ uint32_t cvt2(float lo, float hi) {
    uint32_t r;
    asm("cvt.rn.satfinite.bf16x2.f32 %0, %1, %2;" : "=r"(r) : "f"(hi), "f"(lo));
    return r;
}
__device__ __forceinline__ void split2(float v0, float v1, uint32_t& h2, uint32_t& l2) {
    h2 = cvt2(v0, v1);
    float h0 = __uint_as_float(h2 << 16);
    float h1 = __uint_as_float(h2 & 0xFFFF0000u);
    l2 = cvt2(v0 - h0, v1 - h1);
}
__device__ __forceinline__ void sts32(uint32_t a, uint32_t v) {
    asm volatile("st.shared.b32 [%0], %1;" :: "r"(a), "r"(v) : "memory");
}
__device__ __forceinline__ void mma16816(float* c, const uint4& a, uint32_t b0, uint32_t b1) {
    asm volatile(
        "mma.sync.aligned.m16n8k16.row.col.f32.bf16.bf16.f32 "
        "{%0,%1,%2,%3}, {%4,%5,%6,%7}, {%8,%9}, {%0,%1,%2,%3};"
        : "+f"(c[0]), "+f"(c[1]), "+f"(c[2]), "+f"(c[3])
        : "r"(a.x), "r"(a.y), "r"(a.z), "r"(a.w), "r"(b0), "r"(b1));
}

// ---------------- prep: interpolate + split + pack W fragments ----------------
__global__ void prep_w(const float* __restrict__ W0, const float* __restrict__ W1,
                       const float* __restrict__ DoT)
{
    const int tap = blockIdx.x;
    const int b   = blockIdx.y;
    const float d = DoT[b], od = 1.0f - d;

    const int t    = threadIdx.x;
    const int kf   = t >> 7;
    const int mf   = (t >> 5) & 3;
    const int lane = t & 31;
    const int m    = mf * 16 + (lane >> 2);
    const int k    = kf * 16 + (lane & 3) * 2;

    float v[4][2];
    #pragma unroll
    for (int r = 0; r < 4; r++) {
        const int oc = m + (r & 1) * 8;
        const int ci = k + (r >> 1) * 8;
        const size_t g0 = (size_t)(oc * C_ + ci) * 9 + tap;
        v[r][0] = od * W0[g0] + d * W1[g0];
        v[r][1] = od * W0[g0 + 9] + d * W1[g0 + 9];
    }
    uint4 hi, lo;
    uint32_t* hp = &hi.x;
    uint32_t* lp = &lo.x;
    #pragma unroll
    for (int r = 0; r < 4; r++) split2(v[r][0], v[r][1], hp[r], lp[r]);

    const size_t base = ((((size_t)(b * 9 + tap) * 4 + kf) * 2) * 4 + mf) * 32 + lane;
    g_wfrag[base]       = hi;
    g_wfrag[base + 128] = lo;
}

// ---------------- main kernel ----------------
__global__ __launch_bounds__(THREADS, 1)
void conv_mma(const float* __restrict__ x, float* __restrict__ y)
{
    extern __shared__ char smem[];
    const uint32_t sx = smem_u32(smem);

    const int tid  = threadIdx.x;
    const int wid  = tid >> 5;
    const int lane = tid & 31;
    const int p_   = lane & 3;
    const int q    = lane >> 2;
    const int row  = wid & 7;        // tile row this warp computes
    const int ph   = wid >> 3;       // px half (0: cols 0-31, 1: cols 32-63)
    const int b    = blockIdx.y;

    const float* xb = x + (size_t)b * C_ * NPIX;
    float* yb       = y + (size_t)b * C_ * NPIX;
    const uint4* wf = g_wfrag + (size_t)b * 9 * 1024;

    // ---- prologue: fill all 4 kf-groups of tile 0 into ring slots 0..3 ----
    {
        const int tile0 = blockIdx.x * TPC;
        const int hy0 = (tile0 / 3) * TR - 1;
        const int hx0 = (tile0 % 3) * TC - 1;
        for (int g = 0; g < 4; g++) {
            const uint32_t wsb = sx + (uint32_t)g * GRPB;
            for (int j = 0; j < 8; j++) {
                const int p  = j & 3;
                const int ew = j >> 2;
                const float* src = xb + (size_t)(g * 16 + 2 * p + 8 * ew) * NPIX;
                #pragma unroll
                for (int k = 0; k < 2; k++) {
                    const int rem = tid + k * THREADS;
                    if (rem < HR * HC) {
                        const int r = rem / HC, c = rem - (rem / HC) * HC;
                        const int gy = hy0 + r, gx = hx0 + c;
                        const bool in = ((unsigned)gy < H_) && ((unsigned)gx < W_);
                        float v0 = 0.f, v1 = 0.f;
                        if (in) {
                            v0 = src[gy * W_ + gx];
                            v1 = src[NPIX + gy * W_ + gx];
                        }
                        uint32_t h2, l2;
                        split2(v0, v1, h2, l2);
                        const uint32_t dst = wsb + (uint32_t)(p * PSLOT + r * ROWB + c * 8 + ew * 4);
                        sts32(dst, h2);
                        sts32(dst + LOB, l2);
                    }
                }
            }
        }
    }
    __syncthreads();

    for (int t = 0; t < TPC; t++) {
        const int tile = blockIdx.x * TPC + t;
        const int py0  = (tile / 3) * TR;
        const int px0  = (tile % 3) * TC;
        const bool dofill = (t + 1 < TPC);
        int hy0f = 0, hx0f = 0;
        if (dofill) {
            hy0f = ((tile + 1) / 3) * TR - 1;
            hx0f = ((tile + 1) % 3) * TC - 1;
        }

        float acc[4][4][4];
        #pragma unroll
        for (int mf = 0; mf < 4; mf++)
            #pragma unroll
            for (int cs = 0; cs < 4; cs++) {
                acc[mf][cs][0] = 0.f; acc[mf][cs][1] = 0.f;
                acc[mf][cs][2] = 0.f; acc[mf][cs][3] = 0.f;
            }

        for (int g = 0; g < 4; g++) {                       // kf-group outer
            const uint32_t rsb = sx + (uint32_t)((4 * t + g) % NRING) * GRPB;
            const uint32_t wsb = sx + (uint32_t)((4 * t + g + 4) % NRING) * GRPB;

            // fill pipeline registers (loaded at tap j, stored at tap j+1)
            float fa0 = 0.f, fa1 = 0.f, fb0 = 0.f, fb1 = 0.f;
            uint32_t fda = 0, fdb = 0;
            bool fbv = false;

            for (int j = 0; j < 9; j++) {
                // ---- store fill chunk j-1 ----
                if (dofill && j > 0) {
                    uint32_t h2, l2;
                    split2(fa0, fa1, h2, l2);
                    sts32(fda, h2);
                    sts32(fda + LOB, l2);
                    if (fbv) {
                        split2(fb0, fb1, h2, l2);
                        sts32(fdb, h2);
                        sts32(fdb + LOB, l2);
                    }
                }
                // ---- issue fill loads for chunk j (one (p,e) word-plane) ----
                if (dofill && j < 8) {
                    const int p  = j & 3;
                    const int ew = j >> 2;
                    const float* src = xb + (size_t)(g * 16 + 2 * p + 8 * ew) * NPIX;
                    {
                        const int r = tid / HC, c = tid - (tid / HC) * HC;
                        const int gy = hy0f + r, gx = hx0f + c;
                        const bool in = ((unsigned)gy < H_) && ((unsigned)gx < W_);
                        fa0 = 0.f; fa1 = 0.f;
                        if (in) {
                            fa0 = src[gy * W_ + gx];
                            fa1 = src[NPIX + gy * W_ + gx];
                        }
                        fda = wsb + (uint32_t)(p * PSLOT + r * ROWB + c * 8 + ew * 4);
                    }
                    fbv = (tid < HR * HC - THREADS);   // 660 - 512 = 148
                    if (fbv) {
                        const int rem = tid + THREADS;
                        const int r = rem / HC, c = rem - (rem / HC) * HC;
                        const int gy = hy0f + r, gx = hx0f + c;
                        const bool in = ((unsigned)gy < H_) && ((unsigned)gx < W_);
                        fb0 = 0.f; fb1 = 0.f;
                        if (in) {
                            fb0 = src[gy * W_ + gx];
                            fb1 = src[NPIX + gy * W_ + gx];
                        }
                        fdb = wsb + (uint32_t)(p * PSLOT + r * ROWB + c * 8 + ew * 4);
                    }
                }

                // ---- compute tap j for kf-group g ----
                const int ky = j / 3, kx = j - (j / 3) * 3;
                const uint4* wfk = wf + j * 1024 + g * 256;
                uint4 ah[4], al[4];
                #pragma unroll
                for (int mf = 0; mf < 4; mf++) {
                    ah[mf] = wfk[mf * 32 + lane];
                    al[mf] = wfk[128 + mf * 32 + lane];
                }
                const uint32_t abase = rsb +
                    (uint32_t)(p_ * PSLOT + (row + ky) * ROWB + (ph * 32 + q + kx) * 8);

                #pragma unroll
                for (int cs = 0; cs < 4; cs++) {
                    const uint32_t ad = abase + cs * 64;
                    uint32_t bh0, bh1, bl0, bl1;
                    asm volatile("ld.shared.v2.b32 {%0,%1}, [%2];"
                                 : "=r"(bh0), "=r"(bh1) : "r"(ad));
                    asm volatile("ld.shared.v2.b32 {%0,%1}, [%2];"
                                 : "=r"(bl0), "=r"(bl1) : "r"(ad + LOB));
                    mma16816(acc[0][cs], ah[0], bh0, bh1);
                    mma16816(acc[1][cs], ah[1], bh0, bh1);
                    mma16816(acc[2][cs], ah[2], bh0, bh1);
                    mma16816(acc[3][cs], ah[3], bh0, bh1);
                    mma16816(acc[0][cs], al[0], bh0, bh1);
                    mma16816(acc[1][cs], al[1], bh0, bh1);
                    mma16816(acc[2][cs], al[2], bh0, bh1);
                    mma16816(acc[3][cs], al[3], bh0, bh1);
                    mma16816(acc[0][cs], ah[0], bl0, bl1);
                    mma16816(acc[1][cs], ah[1], bl0, bl1);
                    mma16816(acc[2][cs], ah[2], bl0, bl1);
                    mma16816(acc[3][cs], ah[3], bl0, bl1);
                }
            }
            __syncthreads();   // group boundary: ring slot handoff
        }

        // ---- epilogue: 512 px x 64 oc ----
        const int gy = py0 + row;
        #pragma unroll
        for (int mf = 0; mf < 4; mf++) {
            const int oc = mf * 16 + q;
            #pragma unroll
            for (int cs = 0; cs < 4; cs++) {
                const int gx = px0 + ph * 32 + cs * 8 + 2 * p_;
                float2* o0 = (float2*)(yb + (size_t)oc * NPIX + gy * W_ + gx);
                *o0 = make_float2(acc[mf][cs][0], acc[mf][cs][1]);
                float2* o1 = (float2*)(yb + (size_t)(oc + 8) * NPIX + gy * W_ + gx);
                *o1 = make_float2(acc[mf][cs][2], acc[mf][cs][3]);
            }
        }
    }
}

// ---------------- launch ----------------
extern "C" void kernel_launch(void* const* d_in, const int* in_sizes, int n_in,
                              void* d_out, int out_size)
{
    const float* x   = (const float*)d_in[0];
    const float* DoT = (const float*)d_in[1];
    const float* W0  = (const float*)d_in[2];
    const float* W1  = (const float*)d_in[3];
    float* y = (float*)d_out;

    cudaFuncSetAttribute(conv_mma, cudaFuncAttributeMaxDynamicSharedMemorySize, RINGB);

    prep_w<<<dim3(9, B_), 512>>>(W0, W1, DoT);
    // tiles: 24 row-tiles x 3 col-tiles = 72 per batch; 8 per CTA -> grid.x = 9
    conv_mma<<<dim3(9, B_), THREADS, RINGB>>>(x, y);
}

// round 9
// speedup vs baseline: 1.4963x; 1.4963x over previous
#include <cuda_runtime.h>
#include <cuda_bf16.h>
#include <cstdint>

// ---------------- problem constants ----------------
#define B_   16
#define C_   64
#define H_   192
#define W_   192
#define NPIX (H_ * W_)

// ---------------- tiling (R5 geometry) ----------------
#define TR 8                   // tile rows
#define TC 32                  // tile cols (256 px, 64 oc per tile)
#define HR 10                  // halo rows
#define HC 34                  // halo cols
#define ROWB  272              // 34 * 8 B (word pair e0,e1)
#define SLOTB (HR * ROWB)      // 2720 B per (kf,p) slot
#define IMGB  (16 * SLOTB)     // 43520 B per image (hi or lo)
#define SPLIT (2 * IMGB)       // 87040 B per buffer
#define SMEM_BYTES (2 * SPLIT) // 174080 -> 1 CTA/SM
#define THREADS 384            // 8 compute warps + 4 fill warps
#define TPC 16                 // tiles per CTA (persistent)

// Pre-packed W fragments: [b][tap][kf][hl][mf][lane] uint4 (mma A-frag order)
__device__ uint4 g_wfrag[B_ * 9 * 4 * 2 * 4 * 32];

// ---------------- helpers ----------------
__device__ __forceinline__ uint32_t smem_u32(const void* p) {
    uint32_t a;
    asm("{ .reg .u64 t; cvta.to.shared.u64 t, %1; cvt.u32.u64 %0, t; }" : "=r"(a) : "l"(p));
    return a;
}
__device__ __forceinline__ uint32_t cvt2(float lo, float hi) {
    uint32_t r;
    asm("cvt.rn.satfinite.bf16x2.f32 %0, %1, %2;" : "=r"(r) : "f"(hi), "f"(lo));
    return r;
}
__device__ __forceinline__ void split2(float v0, float v1, uint32_t& h2, uint32_t& l2) {
    h2 = cvt2(v0, v1);
    float h0 = __uint_as_float(h2 << 16);
    float h1 = __uint_as_float(h2 & 0xFFFF0000u);
    l2 = cvt2(v0 - h0, v1 - h1);
}
__device__ __forceinline__ void sts32(uint32_t a, uint32_t v) {
    asm volatile("st.shared.b32 [%0], %1;" :: "r"(a), "r"(v) : "memory");
}
__device__ __forceinline__ void mma16816(float* c, const uint4& a, uint32_t b0, uint32_t b1) {
    asm volatile(
        "mma.sync.aligned.m16n8k16.row.col.f32.bf16.bf16.f32 "
        "{%0,%1,%2,%3}, {%4,%5,%6,%7}, {%8,%9}, {%0,%1,%2,%3};"
        : "+f"(c[0]), "+f"(c[1]), "+f"(c[2]), "+f"(c[3])
        : "r"(a.x), "r"(a.y), "r"(a.z), "r"(a.w), "r"(b0), "r"(b1));
}

// ---------------- prep: interpolate + split + pack W fragments ----------------
__global__ void prep_w(const float* __restrict__ W0, const float* __restrict__ W1,
                       const float* __restrict__ DoT)
{
    const int tap = blockIdx.x;
    const int b   = blockIdx.y;
    const float d = DoT[b], od = 1.0f - d;

    const int t    = threadIdx.x;
    const int kf   = t >> 7;
    const int mf   = (t >> 5) & 3;
    const int lane = t & 31;
    const int m    = mf * 16 + (lane >> 2);
    const int k    = kf * 16 + (lane & 3) * 2;

    float v[4][2];
    #pragma unroll
    for (int r = 0; r < 4; r++) {
        const int oc = m + (r & 1) * 8;
        const int ci = k + (r >> 1) * 8;
        const size_t g0 = (size_t)(oc * C_ + ci) * 9 + tap;
        v[r][0] = od * W0[g0] + d * W1[g0];
        v[r][1] = od * W0[g0 + 9] + d * W1[g0 + 9];
    }
    uint4 hi, lo;
    uint32_t* hp = &hi.x;
    uint32_t* lp = &lo.x;
    #pragma unroll
    for (int r = 0; r < 4; r++) split2(v[r][0], v[r][1], hp[r], lp[r]);

    const size_t base = ((((size_t)(b * 9 + tap) * 4 + kf) * 2) * 4 + mf) * 32 + lane;
    g_wfrag[base]       = hi;
    g_wfrag[base + 128] = lo;
}

// ---------------- main kernel: warp-specialized ----------------
__global__ __launch_bounds__(THREADS, 1)
void conv_mma(const float* __restrict__ x, float* __restrict__ y)
{
    extern __shared__ char smem[];
    const uint32_t sx = smem_u32(smem);

    const int tid  = threadIdx.x;
    const int wid  = tid >> 5;
    const int lane = tid & 31;

    // CTA -> batch / tile range (144 CTAs = 16 batches x 9 CTAs; 16 tiles each)
    const int b    = blockIdx.x / 9;
    const int tib0 = (blockIdx.x % 9) * TPC;

    const float* xb = x + (size_t)b * C_ * NPIX;
    float* yb       = y + (size_t)b * C_ * NPIX;
    const uint4* wf = g_wfrag + (size_t)b * 9 * 1024;

    // ---- fill one tile's halo into buffer (LDG -> split -> STS, R5 layout) ----
    auto fill = [&](int tib, int buf, int start, int stride) {
        const int hy0 = (tib / 6) * TR - 1;
        const int hx0 = (tib % 6) * TC - 1;
        const uint32_t sbuf = sx + (uint32_t)buf * SPLIT;
        for (int j = start; j < 32 * HR * HC; j += stride) {
            const int ci2 = j / (HR * HC);
            const int rem = j - ci2 * (HR * HC);
            const int r   = rem / HC;
            const int c   = rem - r * HC;
            const int gy  = hy0 + r;
            const int gx  = hx0 + c;
            float v0 = 0.f, v1 = 0.f;
            if ((unsigned)gy < H_ && (unsigned)gx < W_) {
                const float* p = xb + (size_t)(2 * ci2) * NPIX + gy * W_ + gx;
                v0 = p[0];
                v1 = p[NPIX];
            }
            uint32_t h2, l2;
            split2(v0, v1, h2, l2);
            const int kfi = ci2 >> 3, l = ci2 & 7, pp = l & 3, e = l >> 2;
            const uint32_t off = (uint32_t)((kfi * 4 + pp) * SLOTB + r * ROWB + c * 8 + e * 4);
            sts32(sbuf + off, h2);
            sts32(sbuf + IMGB + off, l2);
        }
    };

    // ---- prologue: all threads fill tile 0 into buffer 0 ----
    fill(tib0, 0, tid, THREADS);
    __syncthreads();

    const int p_  = lane & 3;
    const int q   = lane >> 2;
    const int row = wid;                 // compute warps: wid 0..7 = tile row

    for (int t = 0; t < TPC; t++) {
        const int tib = tib0 + t;
        const int py0 = (tib / 6) * TR;
        const int px0 = (tib % 6) * TC;

        if (wid < 8) {
            // ================= compute warps: R5 mainloop verbatim =================
            const uint32_t sbuf = sx + (uint32_t)(t & 1) * SPLIT;
            const uint32_t thr_base = sbuf + (uint32_t)(p_ * SLOTB + q * 8);

            float acc[4][4][4];
            #pragma unroll
            for (int mf = 0; mf < 4; mf++)
                #pragma unroll
                for (int cs = 0; cs < 4; cs++) {
                    acc[mf][cs][0] = 0.f; acc[mf][cs][1] = 0.f;
                    acc[mf][cs][2] = 0.f; acc[mf][cs][3] = 0.f;
                }

            for (int tap = 0; tap < 9; tap++) {
                const int ky = tap / 3;
                const int kx = tap - ky * 3;
                const uint4* wft = wf + tap * 1024;
                const uint32_t tap_off = (uint32_t)((row + ky) * ROWB + kx * 8);

                #pragma unroll
                for (int kf = 0; kf < 4; kf++) {
                    const uint4* wfk = wft + kf * 256;
                    uint4 ah[4], al[4];
                    #pragma unroll
                    for (int mf = 0; mf < 4; mf++) {
                        ah[mf] = wfk[mf * 32 + lane];
                        al[mf] = wfk[128 + mf * 32 + lane];
                    }
                    const uint32_t a_base = thr_base + tap_off + (uint32_t)(kf * 4 * SLOTB);

                    #pragma unroll
                    for (int cs = 0; cs < 4; cs++) {
                        const uint32_t ad = a_base + cs * 64;
                        uint32_t bh0, bh1, bl0, bl1;
                        asm volatile("ld.shared.v2.b32 {%0,%1}, [%2];"
                                     : "=r"(bh0), "=r"(bh1) : "r"(ad));
                        asm volatile("ld.shared.v2.b32 {%0,%1}, [%2];"
                                     : "=r"(bl0), "=r"(bl1) : "r"(ad + IMGB));
                        #pragma unroll
                        for (int mf = 0; mf < 4; mf++) mma16816(acc[mf][cs], ah[mf], bh0, bh1);
                        #pragma unroll
                        for (int mf = 0; mf < 4; mf++) mma16816(acc[mf][cs], al[mf], bh0, bh1);
                        #pragma unroll
                        for (int mf = 0; mf < 4; mf++) mma16816(acc[mf][cs], ah[mf], bl0, bl1);
                    }
                }
            }

            // ---- epilogue ----
            const int gy = py0 + row;
            #pragma unroll
            for (int mf = 0; mf < 4; mf++) {
                const int oc = mf * 16 + q;
                #pragma unroll
                for (int cs = 0; cs < 4; cs++) {
                    const int gx = px0 + cs * 8 + 2 * p_;
                    float2* o0 = (float2*)(yb + (size_t)oc * NPIX + gy * W_ + gx);
                    *o0 = make_float2(acc[mf][cs][0], acc[mf][cs][1]);
                    float2* o1 = (float2*)(yb + (size_t)(oc + 8) * NPIX + gy * W_ + gx);
                    *o1 = make_float2(acc[mf][cs][2], acc[mf][cs][3]);
                }
            }
        } else if (t + 1 < TPC) {
            // ================= fill warps: produce tile t+1 =================
            fill(tib + 1, (t + 1) & 1, tid - 256, 128);
        }

        __syncthreads();   // buffer handoff: compute done with buf(t&1), fill done with buf((t+1)&1)
    }
}

// ---------------- launch ----------------
extern "C" void kernel_launch(void* const* d_in, const int* in_sizes, int n_in,
                              void* d_out, int out_size)
{
    const float* x   = (const float*)d_in[0];
    const float* DoT = (const float*)d_in[1];
    const float* W0  = (const float*)d_in[2];
    const float* W1  = (const float*)d_in[3];
    float* y = (float*)d_out;

    cudaFuncSetAttribute(conv_mma, cudaFuncAttributeMaxDynamicSharedMemorySize, SMEM_BYTES);

    prep_w<<<dim3(9, B_), 512>>>(W0, W1, DoT);
    // 2304 tiles total = 144 CTAs x 16 tiles; 9 CTAs per batch
    conv_mma<<<144, THREADS, SMEM_BYTES>>>(x, y);
}